// round 5
// baseline (speedup 1.0000x reference)
#include <cuda_runtime.h>
#include <cuda_bf16.h>

#define NN 50000
#define EE 1600000
#define DD 128
#define GG 512
#define NB 196          // ceil(NN/256)
#define FBLK 782        // ceil(NN/64)

// ---------------- scratch (static device globals; no allocation) ----------------
__device__ __nv_bfloat16 g_A_hi[NN * 256];   // x-part (cols 128..255) hi, bf16
__device__ __nv_bfloat16 g_A_lo[NN * 256];   // x-part lo residual
__device__ __nv_bfloat16 g_Bh[3 * 128 * 256];
__device__ __nv_bfloat16 g_Bl[3 * 128 * 256];
__device__ float g_x1[NN * DD];
__device__ float g_x2[NN * DD];
__device__ float g_invdeg[NN];
__device__ int   g_deg[NN];
__device__ int   g_rowptr[NN];
__device__ int   g_cursor[NN];
__device__ int   g_src[EE];
__device__ int   g_dst[EE];
__device__ int   g_esrc[EE];
__device__ int   g_batch[NN];
__device__ float g_acc[GG];
__device__ float g_cnt[GG];
__device__ int   g_blocksum[NB];
__device__ int   g_blockoff[NB];
__device__ int   g_is64;

// ---------------- dtype probe ----------------
__global__ void detect_dtype_kernel(const void* __restrict__ ei) {
    const long long* p = (const long long*)ei;
    int ok = 1;
#pragma unroll 1
    for (int i = 0; i < 64; i++) {
        long long v = p[i];
        if (v < 0 || v >= NN) ok = 0;
    }
    g_is64 = ok;
}

__global__ void zero_small_kernel() {
    int i = blockIdx.x * blockDim.x + threadIdx.x;
    if (i < NN) g_deg[i] = 0;
    if (i < GG) { g_acc[i] = 0.f; g_cnt[i] = 0.f; }
}

__global__ void convert_edges_kernel(const void* __restrict__ ei) {
    const int is64 = g_is64;
    const long long* p64 = (const long long*)ei;
    const int*       p32 = (const int*)ei;
    for (int i = blockIdx.x * blockDim.x + threadIdx.x; i < EE; i += gridDim.x * blockDim.x) {
        int s, d;
        if (is64) { s = (int)p64[i]; d = (int)p64[EE + i]; }
        else      { s = p32[i];      d = p32[EE + i]; }
        g_src[i] = s;
        g_dst[i] = d;
        atomicAdd(&g_deg[d], 1);
    }
}

// x (external fp32) -> A cols 128..255 hi/lo
__global__ void convert_x_kernel(const float* __restrict__ x) {
    for (int i = blockIdx.x * blockDim.x + threadIdx.x; i < NN * DD; i += gridDim.x * blockDim.x) {
        int row = i >> 7, col = i & 127;
        float v = x[i];
        __nv_bfloat16 h = __float2bfloat16(v);
        __nv_bfloat16 l = __float2bfloat16(v - __bfloat162float(h));
        g_A_hi[row * 256 + 128 + col] = h;
        g_A_lo[row * 256 + 128 + col] = l;
    }
}

// all 3 layers in one launch: B[n][k] = k<128 ? Wl[n][k] : Wr[n][k-128]
__global__ void convert_w_kernel(const float* __restrict__ Wl0, const float* __restrict__ Wr0,
                                 const float* __restrict__ Wl1, const float* __restrict__ Wr1,
                                 const float* __restrict__ Wl2, const float* __restrict__ Wr2) {
    int i = blockIdx.x * blockDim.x + threadIdx.x;   // 0 .. 3*128*256-1
    if (i >= 3 * 128 * 256) return;
    int l = i >> 15;
    int j = i & 32767;
    int n = j >> 8, k = j & 255;
    const float* Wl = (l == 0) ? Wl0 : (l == 1 ? Wl1 : Wl2);
    const float* Wr = (l == 0) ? Wr0 : (l == 1 ? Wr1 : Wr2);
    float v = (k < 128) ? Wl[n * 128 + k] : Wr[n * 128 + (k - 128)];
    __nv_bfloat16 h = __float2bfloat16(v);
    __nv_bfloat16 lo = __float2bfloat16(v - __bfloat162float(h));
    g_Bh[i] = h;
    g_Bl[i] = lo;
}

// ---------------- scan for CSR (+batch conversion folded into part1) ----------------
__global__ void scan_part1_kernel(const void* __restrict__ b) {
    __shared__ int sh[256];
    __shared__ float scnt[GG];
    const int t = threadIdx.x;
    const int i = blockIdx.x * 256 + t;
    // deg block sums
    int v = (i < NN) ? g_deg[i] : 0;
    sh[t] = v;
    // batch conversion with smem-aggregated counts
    scnt[t] = 0.f; scnt[t + 256] = 0.f;
    __syncthreads();
    if (i < NN) {
        const int is64 = g_is64;
        int g = is64 ? (int)((const long long*)b)[i] : ((const int*)b)[i];
        g_batch[i] = g;
        atomicAdd(&scnt[g], 1.f);
    }
    __syncthreads();
    if (scnt[t] != 0.f) atomicAdd(&g_cnt[t], scnt[t]);
    if (scnt[t + 256] != 0.f) atomicAdd(&g_cnt[t + 256], scnt[t + 256]);
    for (int o = 128; o; o >>= 1) {
        if (t < o) sh[t] += sh[t + o];
        __syncthreads();
    }
    if (t == 0) g_blocksum[blockIdx.x] = sh[0];
}

__global__ void scan_part2_kernel() {
    __shared__ int sh[256];
    int t = threadIdx.x;
    sh[t] = (t < NB) ? g_blocksum[t] : 0;
    __syncthreads();
    for (int o = 1; o < 256; o <<= 1) {
        int v = (t >= o) ? sh[t - o] : 0;
        __syncthreads();
        sh[t] += v;
        __syncthreads();
    }
    if (t < NB) g_blockoff[t] = (t == 0) ? 0 : sh[t - 1];
}

__global__ void scan_part3_kernel() {
    __shared__ int sh[256];
    int t = threadIdx.x;
    int i = blockIdx.x * 256 + t;
    int v = (i < NN) ? g_deg[i] : 0;
    sh[t] = v;
    __syncthreads();
    for (int o = 1; o < 256; o <<= 1) {
        int u = (t >= o) ? sh[t - o] : 0;
        __syncthreads();
        sh[t] += u;
        __syncthreads();
    }
    if (i < NN) {
        int excl = sh[t] - v + g_blockoff[blockIdx.x];
        g_rowptr[i] = excl;
        g_cursor[i] = excl;
        g_invdeg[i] = 1.f / fmaxf((float)v, 1.f);
    }
}

__global__ void place_edges_kernel() {
    for (int i = blockIdx.x * blockDim.x + threadIdx.x; i < EE; i += gridDim.x * blockDim.x) {
        int d = g_dst[i];
        int pos = atomicAdd(&g_cursor[d], 1);
        g_esrc[pos] = g_src[i];
    }
}

// ---------------- fused layer: gather (to smem) + split-bf16 MMA + epilogue ----------------
// Block: 64 rows, 256 thr = 8 warps. smem A persistent 64x264 hi/lo; B streamed in k-chunks of 32.
#define MMA16816(d, a, b0_, b1_) \
    asm volatile("mma.sync.aligned.m16n8k16.row.col.f32.bf16.bf16.f32 " \
                 "{%0,%1,%2,%3},{%4,%5,%6,%7},{%8,%9},{%0,%1,%2,%3};" \
                 : "+f"(d[0]), "+f"(d[1]), "+f"(d[2]), "+f"(d[3]) \
                 : "r"(a[0]), "r"(a[1]), "r"(a[2]), "r"(a[3]), "r"(b0_), "r"(b1_))

#define SA_STRIDE 264
#define SB_STRIDE 36
#define SMEM_ELEMS (2 * 64 * SA_STRIDE + 2 * 128 * SB_STRIDE)

__global__ __launch_bounds__(256, 2) void fused_layer_kernel(
    int layer, const float* __restrict__ bias, const float* __restrict__ xext,
    int xsel, int osel, int write_xpart)
{
    extern __shared__ __nv_bfloat16 smem[];
    __nv_bfloat16* sAh = smem;
    __nv_bfloat16* sAl = sAh + 64 * SA_STRIDE;
    __nv_bfloat16* sBh = sAl + 64 * SA_STRIDE;
    __nv_bfloat16* sBl = sBh + 128 * SB_STRIDE;

    const float* __restrict__ xin = (xsel == 0) ? xext : (xsel == 1 ? g_x1 : g_x2);
    float* __restrict__ y = (osel == 1) ? g_x1 : g_x2;
    const __nv_bfloat16* __restrict__ Bh = g_Bh + layer * 128 * 256;
    const __nv_bfloat16* __restrict__ Bl = g_Bl + layer * 128 * 256;

    const int tid  = threadIdx.x;
    const int lane = tid & 31;
    const int warp = tid >> 5;
    const int row0 = blockIdx.x * 64;

    // ---- phase 1a: gather mean for rows warp*8 .. warp*8+7 into sA cols 0..127 ----
#pragma unroll 1
    for (int rr = 0; rr < 8; rr++) {
        const int r = warp * 8 + rr;
        const int grow = row0 + r;
        float4 acc = make_float4(0.f, 0.f, 0.f, 0.f);
        if (grow < NN) {
            int beg = g_rowptr[grow];
            int end = beg + g_deg[grow];
            int e = beg;
#pragma unroll 1
            for (; e + 4 <= end; e += 4) {
                int s0 = g_esrc[e + 0];
                int s1 = g_esrc[e + 1];
                int s2 = g_esrc[e + 2];
                int s3 = g_esrc[e + 3];
                float4 v0 = __ldg((const float4*)xin + (size_t)s0 * 32 + lane);
                float4 v1 = __ldg((const float4*)xin + (size_t)s1 * 32 + lane);
                float4 v2 = __ldg((const float4*)xin + (size_t)s2 * 32 + lane);
                float4 v3 = __ldg((const float4*)xin + (size_t)s3 * 32 + lane);
                acc.x += v0.x + v1.x + v2.x + v3.x;
                acc.y += v0.y + v1.y + v2.y + v3.y;
                acc.z += v0.z + v1.z + v2.z + v3.z;
                acc.w += v0.w + v1.w + v2.w + v3.w;
            }
#pragma unroll 1
            for (; e < end; e++) {
                int s = g_esrc[e];
                float4 v = __ldg((const float4*)xin + (size_t)s * 32 + lane);
                acc.x += v.x; acc.y += v.y; acc.z += v.z; acc.w += v.w;
            }
            float inv = g_invdeg[grow];
            acc.x *= inv; acc.y *= inv; acc.z *= inv; acc.w *= inv;
        }
        float a[4] = {acc.x, acc.y, acc.z, acc.w};
        unsigned int hp[2], lp[2];
#pragma unroll
        for (int p = 0; p < 2; p++) {
            __nv_bfloat16 h0 = __float2bfloat16(a[p * 2 + 0]);
            __nv_bfloat16 h1 = __float2bfloat16(a[p * 2 + 1]);
            __nv_bfloat16 l0 = __float2bfloat16(a[p * 2 + 0] - __bfloat162float(h0));
            __nv_bfloat16 l1 = __float2bfloat16(a[p * 2 + 1] - __bfloat162float(h1));
            hp[p] = (unsigned int)__bfloat16_as_ushort(h0) | ((unsigned int)__bfloat16_as_ushort(h1) << 16);
            lp[p] = (unsigned int)__bfloat16_as_ushort(l0) | ((unsigned int)__bfloat16_as_ushort(l1) << 16);
        }
        *(uint2*)&sAh[r * SA_STRIDE + lane * 4] = make_uint2(hp[0], hp[1]);
        *(uint2*)&sAl[r * SA_STRIDE + lane * 4] = make_uint2(lp[0], lp[1]);
    }

    // ---- phase 1b: stage x-part cols 128..255 from global hi/lo ----
#pragma unroll
    for (int it = 0; it < 8; it++) {
        int s = tid + it * 256;           // 0..2047
        int r = s >> 5;                   // 0..63
        int c = (s & 31) * 4 + 128;       // 128..252
        int grow = row0 + r;
        uint2 h = make_uint2(0u, 0u), l = make_uint2(0u, 0u);
        if (grow < NN) {
            h = *(const uint2*)&g_A_hi[(size_t)grow * 256 + c];
            l = *(const uint2*)&g_A_lo[(size_t)grow * 256 + c];
        }
        *(uint2*)&sAh[r * SA_STRIDE + c] = h;
        *(uint2*)&sAl[r * SA_STRIDE + c] = l;
    }
    __syncthreads();

    // ---- phase 2: MMA. warps: wm in {0,1} (32 rows), wn in {0..3} (32 cols) ----
    const int wm = warp & 1;
    const int wn = warp >> 1;
    const int gr = lane >> 2;
    const int tg2 = (lane & 3) * 2;

    float acc[2][4][4];
#pragma unroll
    for (int mt = 0; mt < 2; mt++)
#pragma unroll
        for (int nt = 0; nt < 4; nt++)
#pragma unroll
            for (int q = 0; q < 4; q++) acc[mt][nt][q] = 0.f;

#pragma unroll 1
    for (int ch = 0; ch < 8; ch++) {
        const int k0 = ch * 32;
#pragma unroll
        for (int it = 0; it < 4; it++) {
            int s = tid + it * 256;       // 0..1023
            int r = s >> 3;               // 0..127
            int c4 = (s & 7) * 4;         // 0..28
            *(uint2*)&sBh[r * SB_STRIDE + c4] = *(const uint2*)&Bh[r * 256 + k0 + c4];
            *(uint2*)&sBl[r * SB_STRIDE + c4] = *(const uint2*)&Bl[r * 256 + k0 + c4];
        }
        __syncthreads();

#pragma unroll
        for (int kk = 0; kk < 32; kk += 16) {
            const int kc = k0 + kk;
            unsigned int ah[2][4], al[2][4];
#pragma unroll
            for (int mt = 0; mt < 2; mt++) {
                int rb = wm * 32 + mt * 16;
                ah[mt][0] = *(const unsigned int*)&sAh[(rb + gr) * SA_STRIDE + kc + tg2];
                ah[mt][1] = *(const unsigned int*)&sAh[(rb + gr + 8) * SA_STRIDE + kc + tg2];
                ah[mt][2] = *(const unsigned int*)&sAh[(rb + gr) * SA_STRIDE + kc + tg2 + 8];
                ah[mt][3] = *(const unsigned int*)&sAh[(rb + gr + 8) * SA_STRIDE + kc + tg2 + 8];
                al[mt][0] = *(const unsigned int*)&sAl[(rb + gr) * SA_STRIDE + kc + tg2];
                al[mt][1] = *(const unsigned int*)&sAl[(rb + gr + 8) * SA_STRIDE + kc + tg2];
                al[mt][2] = *(const unsigned int*)&sAl[(rb + gr) * SA_STRIDE + kc + tg2 + 8];
                al[mt][3] = *(const unsigned int*)&sAl[(rb + gr + 8) * SA_STRIDE + kc + tg2 + 8];
            }
#pragma unroll
            for (int nt = 0; nt < 4; nt++) {
                int nb = wn * 32 + nt * 8 + gr;
                unsigned int bh0 = *(const unsigned int*)&sBh[nb * SB_STRIDE + kk + tg2];
                unsigned int bh1 = *(const unsigned int*)&sBh[nb * SB_STRIDE + kk + tg2 + 8];
                unsigned int bl0 = *(const unsigned int*)&sBl[nb * SB_STRIDE + kk + tg2];
                unsigned int bl1 = *(const unsigned int*)&sBl[nb * SB_STRIDE + kk + tg2 + 8];
#pragma unroll
                for (int mt = 0; mt < 2; mt++) {
                    MMA16816(acc[mt][nt], ah[mt], bh0, bh1);
                    MMA16816(acc[mt][nt], ah[mt], bl0, bl1);
                    MMA16816(acc[mt][nt], al[mt], bh0, bh1);
                }
            }
        }
        __syncthreads();
    }

    // ---- epilogue: bias + relu; write y fp32, optionally next-layer x-part hi/lo ----
#pragma unroll
    for (int mt = 0; mt < 2; mt++) {
#pragma unroll
        for (int nt = 0; nt < 4; nt++) {
            int col = wn * 32 + nt * 8 + tg2;
            float b0 = bias[col], b1 = bias[col + 1];
#pragma unroll
            for (int half = 0; half < 2; half++) {
                int row = row0 + wm * 32 + mt * 16 + gr + half * 8;
                if (row >= NN) continue;
                float v0 = fmaxf(acc[mt][nt][half * 2 + 0] + b0, 0.f);
                float v1 = fmaxf(acc[mt][nt][half * 2 + 1] + b1, 0.f);
                *(float2*)&y[(size_t)row * DD + col] = make_float2(v0, v1);
                if (write_xpart) {
                    __nv_bfloat16 h0 = __float2bfloat16(v0);
                    __nv_bfloat16 h1 = __float2bfloat16(v1);
                    __nv_bfloat16 l0 = __float2bfloat16(v0 - __bfloat162float(h0));
                    __nv_bfloat16 l1 = __float2bfloat16(v1 - __bfloat162float(h1));
                    unsigned int hp = (unsigned int)__bfloat16_as_ushort(h0) | ((unsigned int)__bfloat16_as_ushort(h1) << 16);
                    unsigned int lp = (unsigned int)__bfloat16_as_ushort(l0) | ((unsigned int)__bfloat16_as_ushort(l1) << 16);
                    *(unsigned int*)&g_A_hi[(size_t)row * 256 + 128 + col] = hp;
                    *(unsigned int*)&g_A_lo[(size_t)row * 256 + 128 + col] = lp;
                }
            }
        }
    }
}

// ---------------- pooling ----------------
__global__ void pool_kernel(const float* __restrict__ fcw) {
    long long t = (long long)blockIdx.x * blockDim.x + threadIdx.x;
    int n = (int)(t >> 5);
    if (n >= NN) return;
    int lane = threadIdx.x & 31;
    float4 xv = ((const float4*)g_x1)[(size_t)n * 32 + lane];
    float4 wv = ((const float4*)fcw)[lane];
    float d = xv.x * wv.x + xv.y * wv.y + xv.z * wv.z + xv.w * wv.w;
#pragma unroll
    for (int o = 16; o; o >>= 1) d += __shfl_xor_sync(0xffffffffu, d, o);
    if (lane == 0) atomicAdd(&g_acc[g_batch[n]], d);
}

__global__ void final_kernel(float* __restrict__ out, const float* __restrict__ fcb) {
    int g = blockIdx.x * blockDim.x + threadIdx.x;
    if (g < GG) out[g] = g_acc[g] / fmaxf(g_cnt[g], 1.f) + fcb[0];
}

// ---------------- launch ----------------
extern "C" void kernel_launch(void* const* d_in, const int* in_sizes, int n_in,
                              void* d_out, int out_size) {
    const float* x     = (const float*)d_in[0];
    const void*  ei    = d_in[1];
    const void*  batch = d_in[2];
    const float* Wl[3] = {(const float*)d_in[3], (const float*)d_in[6], (const float*)d_in[9]};
    const float* bb[3] = {(const float*)d_in[4], (const float*)d_in[7], (const float*)d_in[10]};
    const float* Wr[3] = {(const float*)d_in[5], (const float*)d_in[8], (const float*)d_in[11]};
    const float* fcw = (const float*)d_in[12];
    const float* fcb = (const float*)d_in[13];
    float* out = (float*)d_out;

    const int smem_bytes = SMEM_ELEMS * (int)sizeof(__nv_bfloat16);
    cudaFuncSetAttribute(fused_layer_kernel, cudaFuncAttributeMaxDynamicSharedMemorySize, smem_bytes);

    // prep
    detect_dtype_kernel<<<1, 1>>>(ei);
    zero_small_kernel<<<NB, 256>>>();
    convert_edges_kernel<<<4096, 256>>>(ei);
    convert_x_kernel<<<2048, 256>>>(x);
    convert_w_kernel<<<384, 256>>>(Wl[0], Wr[0], Wl[1], Wr[1], Wl[2], Wr[2]);
    scan_part1_kernel<<<NB, 256>>>(batch);
    scan_part2_kernel<<<1, 256>>>();
    scan_part3_kernel<<<NB, 256>>>();
    place_edges_kernel<<<4096, 256>>>();

    // layers (fused gather+combine)
    fused_layer_kernel<<<FBLK, 256, smem_bytes>>>(0, bb[0], x, 0, 1, 1);
    fused_layer_kernel<<<FBLK, 256, smem_bytes>>>(1, bb[1], x, 1, 2, 1);
    fused_layer_kernel<<<FBLK, 256, smem_bytes>>>(2, bb[2], x, 2, 1, 0);

    // pool + fc
    pool_kernel<<<(NN * 32 + 255) / 256, 256>>>(fcw);
    final_kernel<<<(GG + 255) / 256, 256>>>(out, fcb);
}

// round 7
// speedup vs baseline: 1.4059x; 1.4059x over previous
#include <cuda_runtime.h>
#include <cuda_bf16.h>

#define NN 50000
#define EE 1600000
#define DD 128
#define GG 512
#define NB 196          // ceil(NN/256)
#define CBLK 391        // ceil(NN/128)

// ---------------- scratch (static device globals; no allocation) ----------------
__device__ float g_agg[NN * DD];             // fp32 mean-aggregated features
__device__ __nv_bfloat16 g_Bh[3 * 128 * 256];
__device__ __nv_bfloat16 g_Bl[3 * 128 * 256];
__device__ float g_x1[NN * DD];
__device__ float g_x2[NN * DD];
__device__ float g_invdeg[NN];
__device__ int   g_deg[NN];
__device__ int   g_rowptr[NN];
__device__ int   g_cursor[NN];
__device__ int   g_src[EE];
__device__ int   g_dst[EE];
__device__ int   g_esrc[EE];
__device__ int   g_batch[NN];
__device__ float g_acc[GG];
__device__ float g_cnt[GG];
__device__ int   g_blocksum[NB];
__device__ int   g_blockoff[NB];
__device__ int   g_is64;

// ---------------- dtype probe ----------------
__global__ void detect_dtype_kernel(const void* __restrict__ ei) {
    const long long* p = (const long long*)ei;
    int ok = 1;
#pragma unroll 1
    for (int i = 0; i < 64; i++) {
        long long v = p[i];
        if (v < 0 || v >= NN) ok = 0;
    }
    g_is64 = ok;
}

__global__ void zero_small_kernel() {
    int i = blockIdx.x * blockDim.x + threadIdx.x;
    if (i < NN) g_deg[i] = 0;
    if (i < GG) { g_acc[i] = 0.f; g_cnt[i] = 0.f; }
}

__global__ void convert_edges_kernel(const void* __restrict__ ei) {
    const int is64 = g_is64;
    const long long* p64 = (const long long*)ei;
    const int*       p32 = (const int*)ei;
    for (int i = blockIdx.x * blockDim.x + threadIdx.x; i < EE; i += gridDim.x * blockDim.x) {
        int s, d;
        if (is64) { s = (int)p64[i]; d = (int)p64[EE + i]; }
        else      { s = p32[i];      d = p32[EE + i]; }
        g_src[i] = s;
        g_dst[i] = d;
        atomicAdd(&g_deg[d], 1);
    }
}

// all 3 layers in one launch: B[n][k] = k<128 ? Wl[n][k] : Wr[n][k-128]
__global__ void convert_w_kernel(const float* __restrict__ Wl0, const float* __restrict__ Wr0,
                                 const float* __restrict__ Wl1, const float* __restrict__ Wr1,
                                 const float* __restrict__ Wl2, const float* __restrict__ Wr2) {
    int i = blockIdx.x * blockDim.x + threadIdx.x;   // 0 .. 3*128*256-1
    if (i >= 3 * 128 * 256) return;
    int l = i >> 15;
    int j = i & 32767;
    int n = j >> 8, k = j & 255;
    const float* Wl = (l == 0) ? Wl0 : (l == 1 ? Wl1 : Wl2);
    const float* Wr = (l == 0) ? Wr0 : (l == 1 ? Wr1 : Wr2);
    float v = (k < 128) ? Wl[n * 128 + k] : Wr[n * 128 + (k - 128)];
    __nv_bfloat16 h = __float2bfloat16(v);
    __nv_bfloat16 lo = __float2bfloat16(v - __bfloat162float(h));
    g_Bh[i] = h;
    g_Bl[i] = lo;
}

// ---------------- scan for CSR (+batch conversion folded into part1) ----------------
__global__ void scan_part1_kernel(const void* __restrict__ b) {
    __shared__ int sh[256];
    __shared__ float scnt[GG];
    const int t = threadIdx.x;
    const int i = blockIdx.x * 256 + t;
    int v = (i < NN) ? g_deg[i] : 0;
    sh[t] = v;
    scnt[t] = 0.f; scnt[t + 256] = 0.f;
    __syncthreads();
    if (i < NN) {
        const int is64 = g_is64;
        int g = is64 ? (int)((const long long*)b)[i] : ((const int*)b)[i];
        g_batch[i] = g;
        atomicAdd(&scnt[g], 1.f);
    }
    __syncthreads();
    if (scnt[t] != 0.f) atomicAdd(&g_cnt[t], scnt[t]);
    if (scnt[t + 256] != 0.f) atomicAdd(&g_cnt[t + 256], scnt[t + 256]);
    for (int o = 128; o; o >>= 1) {
        if (t < o) sh[t] += sh[t + o];
        __syncthreads();
    }
    if (t == 0) g_blocksum[blockIdx.x] = sh[0];
}

__global__ void scan_part2_kernel() {
    __shared__ int sh[256];
    int t = threadIdx.x;
    sh[t] = (t < NB) ? g_blocksum[t] : 0;
    __syncthreads();
    for (int o = 1; o < 256; o <<= 1) {
        int v = (t >= o) ? sh[t - o] : 0;
        __syncthreads();
        sh[t] += v;
        __syncthreads();
    }
    if (t < NB) g_blockoff[t] = (t == 0) ? 0 : sh[t - 1];
}

__global__ void scan_part3_kernel() {
    __shared__ int sh[256];
    int t = threadIdx.x;
    int i = blockIdx.x * 256 + t;
    int v = (i < NN) ? g_deg[i] : 0;
    sh[t] = v;
    __syncthreads();
    for (int o = 1; o < 256; o <<= 1) {
        int u = (t >= o) ? sh[t - o] : 0;
        __syncthreads();
        sh[t] += u;
        __syncthreads();
    }
    if (i < NN) {
        int excl = sh[t] - v + g_blockoff[blockIdx.x];
        g_rowptr[i] = excl;
        g_cursor[i] = excl;
        g_invdeg[i] = 1.f / fmaxf((float)v, 1.f);
    }
}

__global__ void place_edges_kernel() {
    for (int i = blockIdx.x * blockDim.x + threadIdx.x; i < EE; i += gridDim.x * blockDim.x) {
        int d = g_dst[i];
        int pos = atomicAdd(&g_cursor[d], 1);
        g_esrc[pos] = g_src[i];
    }
}

// ---------------- gather mean -> g_agg (fp32), high-occupancy standalone ----------------
// xsel: 0 = external x, 1 = g_x1, 2 = g_x2
__global__ __launch_bounds__(256) void gather_kernel(const float* __restrict__ xext, int xsel) {
    const float* __restrict__ xin = (xsel == 0) ? xext : (xsel == 1 ? g_x1 : g_x2);
    int warp = (blockIdx.x * 256 + threadIdx.x) >> 5;
    if (warp >= NN) return;
    int lane = threadIdx.x & 31;
    int beg = g_rowptr[warp];
    int end = beg + g_deg[warp];

    float4 acc = make_float4(0.f, 0.f, 0.f, 0.f);
    int e = beg;
#pragma unroll 1
    for (; e + 4 <= end; e += 4) {
        int s0 = g_esrc[e + 0];
        int s1 = g_esrc[e + 1];
        int s2 = g_esrc[e + 2];
        int s3 = g_esrc[e + 3];
        float4 v0 = __ldg((const float4*)xin + (size_t)s0 * 32 + lane);
        float4 v1 = __ldg((const float4*)xin + (size_t)s1 * 32 + lane);
        float4 v2 = __ldg((const float4*)xin + (size_t)s2 * 32 + lane);
        float4 v3 = __ldg((const float4*)xin + (size_t)s3 * 32 + lane);
        acc.x += v0.x + v1.x + v2.x + v3.x;
        acc.y += v0.y + v1.y + v2.y + v3.y;
        acc.z += v0.z + v1.z + v2.z + v3.z;
        acc.w += v0.w + v1.w + v2.w + v3.w;
    }
#pragma unroll 1
    for (; e < end; e++) {
        int s = g_esrc[e];
        float4 v = __ldg((const float4*)xin + (size_t)s * 32 + lane);
        acc.x += v.x; acc.y += v.y; acc.z += v.z; acc.w += v.w;
    }
    float inv = g_invdeg[warp];
    acc.x *= inv; acc.y *= inv; acc.z *= inv; acc.w *= inv;
    ((float4*)g_agg)[(size_t)warp * 32 + lane] = acc;
}

// ---------------- combine via mma.sync bf16 split: Y = relu([agg|x] @ B^T + b) ----------------
// A from fp32 sources: g_agg (cols 0..127) and xsel-selected x (cols 128..255),
// converted to hi/lo bf16 in registers while filling smem.
#define MMA16816(d, a, b0_, b1_) \
    asm volatile("mma.sync.aligned.m16n8k16.row.col.f32.bf16.bf16.f32 " \
                 "{%0,%1,%2,%3},{%4,%5,%6,%7},{%8,%9},{%0,%1,%2,%3};" \
                 : "+f"(d[0]), "+f"(d[1]), "+f"(d[2]), "+f"(d[3]) \
                 : "r"(a[0]), "r"(a[1]), "r"(a[2]), "r"(a[3]), "r"(b0_), "r"(b1_))

__global__ __launch_bounds__(256, 2) void combine_kernel(
    int layer, const float* __restrict__ bias, const float* __restrict__ xext,
    int xsel, int osel, const float* __restrict__ fcw, int do_pool)
{
    const float* __restrict__ xpart = (xsel == 0) ? xext : (xsel == 1 ? g_x1 : g_x2);
    float* __restrict__ y = (osel == 1) ? g_x1 : g_x2;
    const __nv_bfloat16* __restrict__ Bh = g_Bh + layer * 128 * 256;
    const __nv_bfloat16* __restrict__ Bl = g_Bl + layer * 128 * 256;

    __shared__ __nv_bfloat16 sAh[128 * 36];
    __shared__ __nv_bfloat16 sAl[128 * 36];
    __shared__ __nv_bfloat16 sBh[128 * 36];
    __shared__ __nv_bfloat16 sBl[128 * 36];
    __shared__ float sdot[128];

    const int tid = threadIdx.x;
    const int lane = tid & 31;
    const int warp = tid >> 5;
    const int wm = warp & 3;
    const int wn = warp >> 2;
    const int row0 = blockIdx.x * 128;
    const int gr = lane >> 2;
    const int tg2 = (lane & 3) * 2;

    if (do_pool && tid < 128) sdot[tid] = 0.f;

    float acc[2][8][4];
#pragma unroll
    for (int mt = 0; mt < 2; mt++)
#pragma unroll
        for (int nt = 0; nt < 8; nt++)
#pragma unroll
            for (int q = 0; q < 4; q++) acc[mt][nt][q] = 0.f;

#pragma unroll 1
    for (int c = 0; c < 8; c++) {
        const int k0 = c * 32;
        const bool from_x = (k0 >= 128);
        const float* __restrict__ Asrc = from_x ? xpart : g_agg;
        const int kb = from_x ? (k0 - 128) : k0;
#pragma unroll
        for (int it = 0; it < 4; it++) {
            int s = tid + it * 256;         // 0..1023
            int r = s >> 3;                 // 0..127
            int c4 = (s & 7) * 4;           // 0..28
            int grow = row0 + r; if (grow >= NN) grow = NN - 1;
            float4 v = *(const float4*)(Asrc + (size_t)grow * DD + kb + c4);
            __nv_bfloat16 h0 = __float2bfloat16(v.x);
            __nv_bfloat16 h1 = __float2bfloat16(v.y);
            __nv_bfloat16 h2 = __float2bfloat16(v.z);
            __nv_bfloat16 h3 = __float2bfloat16(v.w);
            __nv_bfloat16 l0 = __float2bfloat16(v.x - __bfloat162float(h0));
            __nv_bfloat16 l1 = __float2bfloat16(v.y - __bfloat162float(h1));
            __nv_bfloat16 l2 = __float2bfloat16(v.z - __bfloat162float(h2));
            __nv_bfloat16 l3 = __float2bfloat16(v.w - __bfloat162float(h3));
            uint2 hh, ll;
            hh.x = (unsigned int)__bfloat16_as_ushort(h0) | ((unsigned int)__bfloat16_as_ushort(h1) << 16);
            hh.y = (unsigned int)__bfloat16_as_ushort(h2) | ((unsigned int)__bfloat16_as_ushort(h3) << 16);
            ll.x = (unsigned int)__bfloat16_as_ushort(l0) | ((unsigned int)__bfloat16_as_ushort(l1) << 16);
            ll.y = (unsigned int)__bfloat16_as_ushort(l2) | ((unsigned int)__bfloat16_as_ushort(l3) << 16);
            *(uint2*)&sAh[r * 36 + c4] = hh;
            *(uint2*)&sAl[r * 36 + c4] = ll;
            *(uint2*)&sBh[r * 36 + c4] = *(const uint2*)&Bh[r * 256 + k0 + c4];
            *(uint2*)&sBl[r * 36 + c4] = *(const uint2*)&Bl[r * 256 + k0 + c4];
        }
        __syncthreads();

#pragma unroll
        for (int kk = 0; kk < 32; kk += 16) {
            unsigned int ah[2][4], al[2][4];
#pragma unroll
            for (int mt = 0; mt < 2; mt++) {
                int rb = wm * 32 + mt * 16;
                ah[mt][0] = *(const unsigned int*)&sAh[(rb + gr) * 36 + kk + tg2];
                ah[mt][1] = *(const unsigned int*)&sAh[(rb + gr + 8) * 36 + kk + tg2];
                ah[mt][2] = *(const unsigned int*)&sAh[(rb + gr) * 36 + kk + tg2 + 8];
                ah[mt][3] = *(const unsigned int*)&sAh[(rb + gr + 8) * 36 + kk + tg2 + 8];
                al[mt][0] = *(const unsigned int*)&sAl[(rb + gr) * 36 + kk + tg2];
                al[mt][1] = *(const unsigned int*)&sAl[(rb + gr + 8) * 36 + kk + tg2];
                al[mt][2] = *(const unsigned int*)&sAl[(rb + gr) * 36 + kk + tg2 + 8];
                al[mt][3] = *(const unsigned int*)&sAl[(rb + gr + 8) * 36 + kk + tg2 + 8];
            }
#pragma unroll
            for (int nt = 0; nt < 8; nt++) {
                int nb = wn * 64 + nt * 8 + gr;
                unsigned int bh0 = *(const unsigned int*)&sBh[nb * 36 + kk + tg2];
                unsigned int bh1 = *(const unsigned int*)&sBh[nb * 36 + kk + tg2 + 8];
                unsigned int bl0 = *(const unsigned int*)&sBl[nb * 36 + kk + tg2];
                unsigned int bl1 = *(const unsigned int*)&sBl[nb * 36 + kk + tg2 + 8];
#pragma unroll
                for (int mt = 0; mt < 2; mt++) {
                    MMA16816(acc[mt][nt], ah[mt], bh0, bh1);
                    MMA16816(acc[mt][nt], ah[mt], bl0, bl1);
                    MMA16816(acc[mt][nt], al[mt], bh0, bh1);
                }
            }
        }
        __syncthreads();
    }

    // ---- epilogue ----
    if (!do_pool) {
#pragma unroll
        for (int mt = 0; mt < 2; mt++) {
#pragma unroll
            for (int nt = 0; nt < 8; nt++) {
                int col = wn * 64 + nt * 8 + tg2;
                float b0 = bias[col], b1 = bias[col + 1];
#pragma unroll
                for (int half = 0; half < 2; half++) {
                    int row = row0 + wm * 32 + mt * 16 + gr + half * 8;
                    if (row >= NN) continue;
                    float v0 = fmaxf(acc[mt][nt][half * 2 + 0] + b0, 0.f);
                    float v1 = fmaxf(acc[mt][nt][half * 2 + 1] + b1, 0.f);
                    *(float2*)&y[(size_t)row * DD + col] = make_float2(v0, v1);
                }
            }
        }
    } else {
        // layer 2: fused global-mean-pool partial dot, no y write
#pragma unroll
        for (int mt = 0; mt < 2; mt++) {
#pragma unroll
            for (int nt = 0; nt < 8; nt++) {
                int col = wn * 64 + nt * 8 + tg2;
                float b0 = bias[col], b1 = bias[col + 1];
                float w0 = fcw[col], w1 = fcw[col + 1];
#pragma unroll
                for (int half = 0; half < 2; half++) {
                    int lr = wm * 32 + mt * 16 + gr + half * 8;
                    float v0 = fmaxf(acc[mt][nt][half * 2 + 0] + b0, 0.f);
                    float v1 = fmaxf(acc[mt][nt][half * 2 + 1] + b1, 0.f);
                    atomicAdd(&sdot[lr], v0 * w0 + v1 * w1);
                }
            }
        }
        __syncthreads();
        if (tid < 128) {
            int grow = row0 + tid;
            if (grow < NN) atomicAdd(&g_acc[g_batch[grow]], sdot[tid]);
        }
    }
}

__global__ void final_kernel(float* __restrict__ out, const float* __restrict__ fcb) {
    int g = blockIdx.x * blockDim.x + threadIdx.x;
    if (g < GG) out[g] = g_acc[g] / fmaxf(g_cnt[g], 1.f) + fcb[0];
}

// ---------------- launch ----------------
extern "C" void kernel_launch(void* const* d_in, const int* in_sizes, int n_in,
                              void* d_out, int out_size) {
    const float* x     = (const float*)d_in[0];
    const void*  ei    = d_in[1];
    const void*  batch = d_in[2];
    const float* Wl[3] = {(const float*)d_in[3], (const float*)d_in[6], (const float*)d_in[9]};
    const float* bb[3] = {(const float*)d_in[4], (const float*)d_in[7], (const float*)d_in[10]};
    const float* Wr[3] = {(const float*)d_in[5], (const float*)d_in[8], (const float*)d_in[11]};
    const float* fcw = (const float*)d_in[12];
    const float* fcb = (const float*)d_in[13];
    float* out = (float*)d_out;

    // prep
    detect_dtype_kernel<<<1, 1>>>(ei);
    zero_small_kernel<<<NB, 256>>>();
    convert_edges_kernel<<<4096, 256>>>(ei);
    convert_w_kernel<<<384, 256>>>(Wl[0], Wr[0], Wl[1], Wr[1], Wl[2], Wr[2]);
    scan_part1_kernel<<<NB, 256>>>(batch);
    scan_part2_kernel<<<1, 256>>>();
    scan_part3_kernel<<<NB, 256>>>();
    place_edges_kernel<<<4096, 256>>>();

    const int gather_blocks = (NN * 32 + 255) / 256;

    // layer 0: x -> g_x1
    gather_kernel<<<gather_blocks, 256>>>(x, 0);
    combine_kernel<<<CBLK, 256>>>(0, bb[0], x, 0, 1, fcw, 0);
    // layer 1: g_x1 -> g_x2
    gather_kernel<<<gather_blocks, 256>>>(x, 1);
    combine_kernel<<<CBLK, 256>>>(1, bb[1], x, 1, 2, fcw, 0);
    // layer 2: g_x2 -> pooled dots (no y)
    gather_kernel<<<gather_blocks, 256>>>(x, 2);
    combine_kernel<<<CBLK, 256>>>(2, bb[2], x, 2, 0, fcw, 1);

    final_kernel<<<(GG + 255) / 256, 256>>>(out, fcb);
}

// round 8
// speedup vs baseline: 1.4732x; 1.0478x over previous
#include <cuda_runtime.h>
#include <cuda_bf16.h>
#include <cuda_fp16.h>

#define NN 50000
#define EE 1600000
#define DD 128
#define GG 512
#define NB 196          // ceil(NN/256)
#define CBLK 391        // ceil(NN/128)

// ---------------- scratch (static device globals; no allocation) ----------------
__device__ float g_agg[NN * DD];             // fp32 mean-aggregated features
__device__ __half g_xh[NN * DD];             // fp16 copy of current layer input (gather payload)
__device__ __nv_bfloat16 g_Bh[3 * 128 * 256];
__device__ __nv_bfloat16 g_Bl[3 * 128 * 256];
__device__ float g_x1[NN * DD];
__device__ float g_x2[NN * DD];
__device__ float g_invdeg[NN];
__device__ int   g_deg[NN];
__device__ int   g_rowptr[NN];
__device__ int   g_cursor[NN];
__device__ int   g_src[EE];
__device__ int   g_dst[EE];
__device__ int   g_esrc[EE];
__device__ int   g_batch[NN];
__device__ float g_acc[GG];
__device__ float g_cnt[GG];
__device__ int   g_blocksum[NB];
__device__ int   g_blockoff[NB];
__device__ int   g_is64;

// ---------------- dtype probe ----------------
__global__ void detect_dtype_kernel(const void* __restrict__ ei) {
    const long long* p = (const long long*)ei;
    int ok = 1;
#pragma unroll 1
    for (int i = 0; i < 64; i++) {
        long long v = p[i];
        if (v < 0 || v >= NN) ok = 0;
    }
    g_is64 = ok;
}

__global__ void zero_small_kernel() {
    int i = blockIdx.x * blockDim.x + threadIdx.x;
    if (i < NN) g_deg[i] = 0;
    if (i < GG) { g_acc[i] = 0.f; g_cnt[i] = 0.f; }
}

__global__ void convert_edges_kernel(const void* __restrict__ ei) {
    const int is64 = g_is64;
    const long long* p64 = (const long long*)ei;
    const int*       p32 = (const int*)ei;
    for (int i = blockIdx.x * blockDim.x + threadIdx.x; i < EE; i += gridDim.x * blockDim.x) {
        int s, d;
        if (is64) { s = (int)p64[i]; d = (int)p64[EE + i]; }
        else      { s = p32[i];      d = p32[EE + i]; }
        g_src[i] = s;
        g_dst[i] = d;
        atomicAdd(&g_deg[d], 1);
    }
}

// x (fp32) -> g_xh (fp16) for the layer-0 gather
__global__ void convert_x_fp16_kernel(const float* __restrict__ x) {
    int n = NN * DD / 2;
    for (int i = blockIdx.x * blockDim.x + threadIdx.x; i < n; i += gridDim.x * blockDim.x) {
        float2 v = ((const float2*)x)[i];
        ((__half2*)g_xh)[i] = __floats2half2_rn(v.x, v.y);
    }
}

// all 3 layers in one launch: B[n][k] = k<128 ? Wl[n][k] : Wr[n][k-128]
__global__ void convert_w_kernel(const float* __restrict__ Wl0, const float* __restrict__ Wr0,
                                 const float* __restrict__ Wl1, const float* __restrict__ Wr1,
                                 const float* __restrict__ Wl2, const float* __restrict__ Wr2) {
    int i = blockIdx.x * blockDim.x + threadIdx.x;   // 0 .. 3*128*256-1
    if (i >= 3 * 128 * 256) return;
    int l = i >> 15;
    int j = i & 32767;
    int n = j >> 8, k = j & 255;
    const float* Wl = (l == 0) ? Wl0 : (l == 1 ? Wl1 : Wl2);
    const float* Wr = (l == 0) ? Wr0 : (l == 1 ? Wr1 : Wr2);
    float v = (k < 128) ? Wl[n * 128 + k] : Wr[n * 128 + (k - 128)];
    __nv_bfloat16 h = __float2bfloat16(v);
    __nv_bfloat16 lo = __float2bfloat16(v - __bfloat162float(h));
    g_Bh[i] = h;
    g_Bl[i] = lo;
}

// ---------------- scan for CSR (+batch conversion folded into part1) ----------------
__global__ void scan_part1_kernel(const void* __restrict__ b) {
    __shared__ int sh[256];
    __shared__ float scnt[GG];
    const int t = threadIdx.x;
    const int i = blockIdx.x * 256 + t;
    int v = (i < NN) ? g_deg[i] : 0;
    sh[t] = v;
    scnt[t] = 0.f; scnt[t + 256] = 0.f;
    __syncthreads();
    if (i < NN) {
        const int is64 = g_is64;
        int g = is64 ? (int)((const long long*)b)[i] : ((const int*)b)[i];
        g_batch[i] = g;
        atomicAdd(&scnt[g], 1.f);
    }
    __syncthreads();
    if (scnt[t] != 0.f) atomicAdd(&g_cnt[t], scnt[t]);
    if (scnt[t + 256] != 0.f) atomicAdd(&g_cnt[t + 256], scnt[t + 256]);
    for (int o = 128; o; o >>= 1) {
        if (t < o) sh[t] += sh[t + o];
        __syncthreads();
    }
    if (t == 0) g_blocksum[blockIdx.x] = sh[0];
}

__global__ void scan_part2_kernel() {
    __shared__ int sh[256];
    int t = threadIdx.x;
    sh[t] = (t < NB) ? g_blocksum[t] : 0;
    __syncthreads();
    for (int o = 1; o < 256; o <<= 1) {
        int v = (t >= o) ? sh[t - o] : 0;
        __syncthreads();
        sh[t] += v;
        __syncthreads();
    }
    if (t < NB) g_blockoff[t] = (t == 0) ? 0 : sh[t - 1];
}

__global__ void scan_part3_kernel() {
    __shared__ int sh[256];
    int t = threadIdx.x;
    int i = blockIdx.x * 256 + t;
    int v = (i < NN) ? g_deg[i] : 0;
    sh[t] = v;
    __syncthreads();
    for (int o = 1; o < 256; o <<= 1) {
        int u = (t >= o) ? sh[t - o] : 0;
        __syncthreads();
        sh[t] += u;
        __syncthreads();
    }
    if (i < NN) {
        int excl = sh[t] - v + g_blockoff[blockIdx.x];
        g_rowptr[i] = excl;
        g_cursor[i] = excl;
        g_invdeg[i] = 1.f / fmaxf((float)v, 1.f);
    }
}

__global__ void place_edges_kernel() {
    for (int i = blockIdx.x * blockDim.x + threadIdx.x; i < EE; i += gridDim.x * blockDim.x) {
        int d = g_dst[i];
        int pos = atomicAdd(&g_cursor[d], 1);
        g_esrc[pos] = g_src[i];
    }
}

// ---------------- gather mean -> g_agg (fp32), reads fp16 rows (256B/row) ----------------
__global__ __launch_bounds__(256) void gather_kernel() {
    int warp = (blockIdx.x * 256 + threadIdx.x) >> 5;
    if (warp >= NN) return;
    int lane = threadIdx.x & 31;
    int beg = g_rowptr[warp];
    int end = beg + g_deg[warp];

    float4 acc = make_float4(0.f, 0.f, 0.f, 0.f);
    int e = beg;
#pragma unroll 1
    for (; e + 4 <= end; e += 4) {
        int s0 = g_esrc[e + 0];
        int s1 = g_esrc[e + 1];
        int s2 = g_esrc[e + 2];
        int s3 = g_esrc[e + 3];
        uint2 u0 = __ldg((const uint2*)g_xh + (size_t)s0 * 32 + lane);
        uint2 u1 = __ldg((const uint2*)g_xh + (size_t)s1 * 32 + lane);
        uint2 u2 = __ldg((const uint2*)g_xh + (size_t)s2 * 32 + lane);
        uint2 u3 = __ldg((const uint2*)g_xh + (size_t)s3 * 32 + lane);
#pragma unroll
        for (int q = 0; q < 4; q++) {
            uint2 u = (q == 0) ? u0 : (q == 1) ? u1 : (q == 2) ? u2 : u3;
            float2 p0 = __half22float2(*(__half2*)&u.x);
            float2 p1 = __half22float2(*(__half2*)&u.y);
            acc.x += p0.x; acc.y += p0.y; acc.z += p1.x; acc.w += p1.y;
        }
    }
#pragma unroll 1
    for (; e < end; e++) {
        int s = g_esrc[e];
        uint2 u = __ldg((const uint2*)g_xh + (size_t)s * 32 + lane);
        float2 p0 = __half22float2(*(__half2*)&u.x);
        float2 p1 = __half22float2(*(__half2*)&u.y);
        acc.x += p0.x; acc.y += p0.y; acc.z += p1.x; acc.w += p1.y;
    }
    float inv = g_invdeg[warp];
    acc.x *= inv; acc.y *= inv; acc.z *= inv; acc.w *= inv;
    ((float4*)g_agg)[(size_t)warp * 32 + lane] = acc;
}

// ---------------- combine via mma.sync bf16 split: Y = relu([agg|x] @ B^T + b) ----------------
#define MMA16816(d, a, b0_, b1_) \
    asm volatile("mma.sync.aligned.m16n8k16.row.col.f32.bf16.bf16.f32 " \
                 "{%0,%1,%2,%3},{%4,%5,%6,%7},{%8,%9},{%0,%1,%2,%3};" \
                 : "+f"(d[0]), "+f"(d[1]), "+f"(d[2]), "+f"(d[3]) \
                 : "r"(a[0]), "r"(a[1]), "r"(a[2]), "r"(a[3]), "r"(b0_), "r"(b1_))

__global__ __launch_bounds__(256, 2) void combine_kernel(
    int layer, const float* __restrict__ bias, const float* __restrict__ xext,
    int xsel, int osel, const float* __restrict__ fcw, int do_pool)
{
    const float* __restrict__ xpart = (xsel == 0) ? xext : (xsel == 1 ? g_x1 : g_x2);
    float* __restrict__ y = (osel == 1) ? g_x1 : g_x2;
    const __nv_bfloat16* __restrict__ Bh = g_Bh + layer * 128 * 256;
    const __nv_bfloat16* __restrict__ Bl = g_Bl + layer * 128 * 256;

    __shared__ __nv_bfloat16 sAh[128 * 36];
    __shared__ __nv_bfloat16 sAl[128 * 36];
    __shared__ __nv_bfloat16 sBh[128 * 36];
    __shared__ __nv_bfloat16 sBl[128 * 36];
    __shared__ float sdot[128];

    const int tid = threadIdx.x;
    const int lane = tid & 31;
    const int warp = tid >> 5;
    const int wm = warp & 3;
    const int wn = warp >> 2;
    const int row0 = blockIdx.x * 128;
    const int gr = lane >> 2;
    const int tg2 = (lane & 3) * 2;

    if (do_pool && tid < 128) sdot[tid] = 0.f;

    float acc[2][8][4];
#pragma unroll
    for (int mt = 0; mt < 2; mt++)
#pragma unroll
        for (int nt = 0; nt < 8; nt++)
#pragma unroll
            for (int q = 0; q < 4; q++) acc[mt][nt][q] = 0.f;

#pragma unroll 1
    for (int c = 0; c < 8; c++) {
        const int k0 = c * 32;
        const bool from_x = (k0 >= 128);
        const float* __restrict__ Asrc = from_x ? xpart : g_agg;
        const int kb = from_x ? (k0 - 128) : k0;
#pragma unroll
        for (int it = 0; it < 4; it++) {
            int s = tid + it * 256;         // 0..1023
            int r = s >> 3;                 // 0..127
            int c4 = (s & 7) * 4;           // 0..28
            int grow = row0 + r; if (grow >= NN) grow = NN - 1;
            float4 v = *(const float4*)(Asrc + (size_t)grow * DD + kb + c4);
            __nv_bfloat16 h0 = __float2bfloat16(v.x);
            __nv_bfloat16 h1 = __float2bfloat16(v.y);
            __nv_bfloat16 h2 = __float2bfloat16(v.z);
            __nv_bfloat16 h3 = __float2bfloat16(v.w);
            __nv_bfloat16 l0 = __float2bfloat16(v.x - __bfloat162float(h0));
            __nv_bfloat16 l1 = __float2bfloat16(v.y - __bfloat162float(h1));
            __nv_bfloat16 l2 = __float2bfloat16(v.z - __bfloat162float(h2));
            __nv_bfloat16 l3 = __float2bfloat16(v.w - __bfloat162float(h3));
            uint2 hh, ll;
            hh.x = (unsigned int)__bfloat16_as_ushort(h0) | ((unsigned int)__bfloat16_as_ushort(h1) << 16);
            hh.y = (unsigned int)__bfloat16_as_ushort(h2) | ((unsigned int)__bfloat16_as_ushort(h3) << 16);
            ll.x = (unsigned int)__bfloat16_as_ushort(l0) | ((unsigned int)__bfloat16_as_ushort(l1) << 16);
            ll.y = (unsigned int)__bfloat16_as_ushort(l2) | ((unsigned int)__bfloat16_as_ushort(l3) << 16);
            *(uint2*)&sAh[r * 36 + c4] = hh;
            *(uint2*)&sAl[r * 36 + c4] = ll;
            *(uint2*)&sBh[r * 36 + c4] = *(const uint2*)&Bh[r * 256 + k0 + c4];
            *(uint2*)&sBl[r * 36 + c4] = *(const uint2*)&Bl[r * 256 + k0 + c4];
        }
        __syncthreads();

#pragma unroll
        for (int kk = 0; kk < 32; kk += 16) {
            unsigned int ah[2][4], al[2][4];
#pragma unroll
            for (int mt = 0; mt < 2; mt++) {
                int rb = wm * 32 + mt * 16;
                ah[mt][0] = *(const unsigned int*)&sAh[(rb + gr) * 36 + kk + tg2];
                ah[mt][1] = *(const unsigned int*)&sAh[(rb + gr + 8) * 36 + kk + tg2];
                ah[mt][2] = *(const unsigned int*)&sAh[(rb + gr) * 36 + kk + tg2 + 8];
                ah[mt][3] = *(const unsigned int*)&sAh[(rb + gr + 8) * 36 + kk + tg2 + 8];
                al[mt][0] = *(const unsigned int*)&sAl[(rb + gr) * 36 + kk + tg2];
                al[mt][1] = *(const unsigned int*)&sAl[(rb + gr + 8) * 36 + kk + tg2];
                al[mt][2] = *(const unsigned int*)&sAl[(rb + gr) * 36 + kk + tg2 + 8];
                al[mt][3] = *(const unsigned int*)&sAl[(rb + gr + 8) * 36 + kk + tg2 + 8];
            }
#pragma unroll
            for (int nt = 0; nt < 8; nt++) {
                int nb = wn * 64 + nt * 8 + gr;
                unsigned int bh0 = *(const unsigned int*)&sBh[nb * 36 + kk + tg2];
                unsigned int bh1 = *(const unsigned int*)&sBh[nb * 36 + kk + tg2 + 8];
                unsigned int bl0 = *(const unsigned int*)&sBl[nb * 36 + kk + tg2];
                unsigned int bl1 = *(const unsigned int*)&sBl[nb * 36 + kk + tg2 + 8];
#pragma unroll
                for (int mt = 0; mt < 2; mt++) {
                    MMA16816(acc[mt][nt], ah[mt], bh0, bh1);
                    MMA16816(acc[mt][nt], ah[mt], bl0, bl1);
                    MMA16816(acc[mt][nt], al[mt], bh0, bh1);
                }
            }
        }
        __syncthreads();
    }

    // ---- epilogue ----
    if (!do_pool) {
#pragma unroll
        for (int mt = 0; mt < 2; mt++) {
#pragma unroll
            for (int nt = 0; nt < 8; nt++) {
                int col = wn * 64 + nt * 8 + tg2;
                float b0 = bias[col], b1 = bias[col + 1];
#pragma unroll
                for (int half = 0; half < 2; half++) {
                    int row = row0 + wm * 32 + mt * 16 + gr + half * 8;
                    if (row >= NN) continue;
                    float v0 = fmaxf(acc[mt][nt][half * 2 + 0] + b0, 0.f);
                    float v1 = fmaxf(acc[mt][nt][half * 2 + 1] + b1, 0.f);
                    *(float2*)&y[(size_t)row * DD + col] = make_float2(v0, v1);
                    // fp16 copy for the next layer's gather
                    *(__half2*)&g_xh[(size_t)row * DD + col] = __floats2half2_rn(v0, v1);
                }
            }
        }
    } else {
        // layer 2: fused global-mean-pool partial dot, no y write
#pragma unroll
        for (int mt = 0; mt < 2; mt++) {
#pragma unroll
            for (int nt = 0; nt < 8; nt++) {
                int col = wn * 64 + nt * 8 + tg2;
                float b0 = bias[col], b1 = bias[col + 1];
                float w0 = fcw[col], w1 = fcw[col + 1];
#pragma unroll
                for (int half = 0; half < 2; half++) {
                    int lr = wm * 32 + mt * 16 + gr + half * 8;
                    float v0 = fmaxf(acc[mt][nt][half * 2 + 0] + b0, 0.f);
                    float v1 = fmaxf(acc[mt][nt][half * 2 + 1] + b1, 0.f);
                    atomicAdd(&sdot[lr], v0 * w0 + v1 * w1);
                }
            }
        }
        __syncthreads();
        if (tid < 128) {
            int grow = row0 + tid;
            if (grow < NN) atomicAdd(&g_acc[g_batch[grow]], sdot[tid]);
        }
    }
}

__global__ void final_kernel(float* __restrict__ out, const float* __restrict__ fcb) {
    int g = blockIdx.x * blockDim.x + threadIdx.x;
    if (g < GG) out[g] = g_acc[g] / fmaxf(g_cnt[g], 1.f) + fcb[0];
}

// ---------------- launch ----------------
extern "C" void kernel_launch(void* const* d_in, const int* in_sizes, int n_in,
                              void* d_out, int out_size) {
    const float* x     = (const float*)d_in[0];
    const void*  ei    = d_in[1];
    const void*  batch = d_in[2];
    const float* Wl[3] = {(const float*)d_in[3], (const float*)d_in[6], (const float*)d_in[9]};
    const float* bb[3] = {(const float*)d_in[4], (const float*)d_in[7], (const float*)d_in[10]};
    const float* Wr[3] = {(const float*)d_in[5], (const float*)d_in[8], (const float*)d_in[11]};
    const float* fcw = (const float*)d_in[12];
    const float* fcb = (const float*)d_in[13];
    float* out = (float*)d_out;

    // prep
    detect_dtype_kernel<<<1, 1>>>(ei);
    zero_small_kernel<<<NB, 256>>>();
    convert_edges_kernel<<<4096, 256>>>(ei);
    convert_x_fp16_kernel<<<2048, 256>>>(x);
    convert_w_kernel<<<384, 256>>>(Wl[0], Wr[0], Wl[1], Wr[1], Wl[2], Wr[2]);
    scan_part1_kernel<<<NB, 256>>>(batch);
    scan_part2_kernel<<<1, 256>>>();
    scan_part3_kernel<<<NB, 256>>>();
    place_edges_kernel<<<4096, 256>>>();

    const int gather_blocks = (NN * 32 + 255) / 256;

    // layer 0: x -> g_x1 (+g_xh)
    gather_kernel<<<gather_blocks, 256>>>();
    combine_kernel<<<CBLK, 256>>>(0, bb[0], x, 0, 1, fcw, 0);
    // layer 1: g_x1 -> g_x2 (+g_xh)
    gather_kernel<<<gather_blocks, 256>>>();
    combine_kernel<<<CBLK, 256>>>(1, bb[1], x, 1, 2, fcw, 0);
    // layer 2: g_x2 -> pooled dots (no y)
    gather_kernel<<<gather_blocks, 256>>>();
    combine_kernel<<<CBLK, 256>>>(2, bb[2], x, 2, 0, fcw, 1);

    final_kernel<<<(GG + 255) / 256, 256>>>(out, fcb);
}